// round 11
// baseline (speedup 1.0000x reference)
#include <cuda_runtime.h>
#include <cuda_bf16.h>
#include <cuda_fp16.h>
#include <cstdint>

#define MAXN 100000
#define MAXE 1600000
#define C 128
#define NBMAX 1024
#define KP 136   // padded K row length (bf16): 272B rows -> conflict-free ldmatrix

// ================= static scratch =================
__device__ int   g_cnt[MAXN];
__device__ int   g_rowptr[MAXN + 1];
__device__ float g_dinv[MAXN];
__device__ int   g_srcs[MAXE];
__device__ int   g_rank[MAXE];
__device__ int   g_blocksum[NBMAX];
__device__ int   g_blockoff[NBMAX];
__device__ __half g_xh[(size_t)MAXN * C];           // dinv-scaled x in fp16
__device__ __half g_h [(size_t)MAXN * C];           // dinv*relu(layer1) in fp16
__device__ __nv_bfloat16 g_axhi[(size_t)MAXN * C];  // agg(x) bf16 hi
__device__ __nv_bfloat16 g_axlo[(size_t)MAXN * C];  // agg(x) bf16 lo
__device__ __nv_bfloat16 g_ahhi[(size_t)MAXN * C];  // agg(h) bf16 hi
__device__ __nv_bfloat16 g_ahlo[(size_t)MAXN * C];  // agg(h) bf16 lo
__device__ __nv_bfloat16 g_w1hi[C * C], g_w1lo[C * C];  // W1^T  [n][k] bf16 hi/lo
__device__ __nv_bfloat16 g_w2hi[C * C], g_w2lo[C * C];  // [Wmu|Wls]^T
__device__ float g_b2[C];

// ================= helpers =================
__device__ __forceinline__ uint32_t smem_u32(const void* p) {
    uint32_t a;
    asm("{ .reg .u64 t; cvta.to.shared.u64 t, %1; cvt.u32.u64 %0, t; }" : "=r"(a) : "l"(p));
    return a;
}
__device__ __forceinline__ void ldsm_x4(uint32_t* r, uint32_t addr) {
    asm volatile("ldmatrix.sync.aligned.m8n8.x4.shared.b16 {%0,%1,%2,%3}, [%4];"
        : "=r"(r[0]), "=r"(r[1]), "=r"(r[2]), "=r"(r[3]) : "r"(addr));
}
__device__ __forceinline__ void mma16816(float* d, const uint32_t* a, const uint32_t* b) {
    asm volatile("mma.sync.aligned.m16n8k16.row.col.f32.bf16.bf16.f32 "
        "{%0,%1,%2,%3}, {%4,%5,%6,%7}, {%8,%9}, {%0,%1,%2,%3};"
        : "+f"(d[0]), "+f"(d[1]), "+f"(d[2]), "+f"(d[3])
        : "r"(a[0]), "r"(a[1]), "r"(a[2]), "r"(a[3]), "r"(b[0]), "r"(b[1]));
}
__device__ __forceinline__ uint32_t pack_bf2(float a, float b) {
    __nv_bfloat162 t = __halves2bfloat162(__float2bfloat16_rn(a), __float2bfloat16_rn(b));
    return *reinterpret_cast<uint32_t*>(&t);
}
__device__ __forceinline__ float4 h4f(uint2 u) {
    float2 fa = __half22float2(*reinterpret_cast<__half2*>(&u.x));
    float2 fb = __half22float2(*reinterpret_cast<__half2*>(&u.y));
    return make_float4(fa.x, fa.y, fb.x, fb.y);
}

// ================= CSR build =================
__global__ void init_kernel(int n) {
    int i = blockIdx.x * blockDim.x + threadIdx.x;
    if (i < n) g_cnt[i] = 0;
}
// count + record per-edge rank (makes scatter atomic-free)
__global__ void count_kernel(const int* __restrict__ col, int e) {
    int i = blockIdx.x * blockDim.x + threadIdx.x;
    if (i < e) g_rank[i] = atomicAdd(&g_cnt[col[i]], 1);
}
__global__ void scanA_kernel(int n) {
    __shared__ int red[256];
    int i = blockIdx.x * 256 + threadIdx.x;
    red[threadIdx.x] = (i < n) ? g_cnt[i] : 0;
    __syncthreads();
    for (int off = 128; off > 0; off >>= 1) {
        if (threadIdx.x < off) red[threadIdx.x] += red[threadIdx.x + off];
        __syncthreads();
    }
    if (threadIdx.x == 0) g_blocksum[blockIdx.x] = red[0];
}
__global__ void scanB_kernel(int nb, int n) {
    __shared__ int s[NBMAX];
    int t = threadIdx.x;
    int v = (t < nb) ? g_blocksum[t] : 0;
    s[t] = v;
    __syncthreads();
    for (int off = 1; off < NBMAX; off <<= 1) {
        int u = (t >= off) ? s[t - off] : 0;
        __syncthreads();
        s[t] += u;
        __syncthreads();
    }
    if (t < nb) g_blockoff[t] = s[t] - v;
    if (t == NBMAX - 1) g_rowptr[n] = s[NBMAX - 1];
}
__global__ void scanC_kernel(int n) {
    __shared__ int s[256];
    int i = blockIdx.x * 256 + threadIdx.x;
    int c = (i < n) ? g_cnt[i] : 0;
    s[threadIdx.x] = c;
    __syncthreads();
    for (int off = 1; off < 256; off <<= 1) {
        int u = (threadIdx.x >= off) ? s[threadIdx.x - off] : 0;
        __syncthreads();
        s[threadIdx.x] += u;
        __syncthreads();
    }
    if (i < n) {
        g_rowptr[i] = g_blockoff[blockIdx.x] + s[threadIdx.x] - c;
        g_dinv[i]   = rsqrtf((float)(c + 1));
    }
}
// atomic-free scatter using precomputed ranks
__global__ void scatter_kernel(const int* __restrict__ row, const int* __restrict__ col, int e) {
    int i = blockIdx.x * blockDim.x + threadIdx.x;
    if (i < e) {
        int c = col[i];
        g_srcs[g_rowptr[c] + g_rank[i]] = row[i];
    }
}

// x -> dinv-scaled fp16 (streaming)
__global__ void scale_half_kernel(const float* __restrict__ x, int n) {
    int i = blockIdx.x * blockDim.x + threadIdx.x;
    if (i >= n * 32) return;
    float d = g_dinv[i >> 5];
    float4 v = ((const float4*)x)[i];
    __half2 a = __floats2half2_rn(v.x * d, v.y * d);
    __half2 b = __floats2half2_rn(v.z * d, v.w * d);
    ((uint2*)g_xh)[i] = make_uint2(*reinterpret_cast<uint32_t*>(&a),
                                   *reinterpret_cast<uint32_t*>(&b));
}

// pack transposed bf16 hi/lo W images: Bt[nn][k] = W[k][nn]
__global__ void packW_kernel(const float* __restrict__ W1,
                             const float* __restrict__ Wmu, const float* __restrict__ bmu,
                             const float* __restrict__ Wls, const float* __restrict__ bls) {
    int k = blockIdx.x;
    int nn = threadIdx.x;
    int layer = blockIdx.y;
    float w;
    if (layer == 0) w = W1[k * 128 + nn];
    else            w = (nn < 64) ? Wmu[k * 64 + nn] : Wls[k * 64 + (nn - 64)];
    __nv_bfloat16 bh = __float2bfloat16_rn(w);
    __nv_bfloat16 bl = __float2bfloat16_rn(w - __bfloat162float(bh));
    if (layer == 0) { g_w1hi[nn * 128 + k] = bh; g_w1lo[nn * 128 + k] = bl; }
    else {
        g_w2hi[nn * 128 + k] = bh; g_w2lo[nn * 128 + k] = bl;
        if (k == 0) g_b2[nn] = (nn < 64) ? bmu[nn] : bls[nn - 64];
    }
}

// ================= aggregation: warp/node, coalesced idx window + shfl =============
// One coalesced LDG fetches up to 32 edge indices; feature-load addresses then come
// from register shfl, so the idx->feature L2 latency chain fires once per 32 edges.
// PHASE 0: src = g_xh -> g_axhi/lo       PHASE 1: src = g_h -> g_ahhi/lo
template <int PHASE>
__global__ void agg_kernel(int n) {
    int w = (blockIdx.x * blockDim.x + threadIdx.x) >> 5;
    int lane = threadIdx.x & 31;
    if (w >= n) return;
    const uint2* __restrict__ s2 = (PHASE == 0) ? (const uint2*)g_xh : (const uint2*)g_h;

    float dw = g_dinv[w];
    float4 acc = h4f(s2[(size_t)w * 32 + lane]);   // self term (pre-scaled by dinv)

    int p = g_rowptr[w];
    int end = g_rowptr[w + 1];
    int nb = end - p;

    while (nb > 0) {
        int take = (nb < 32) ? nb : 32;
        int myidx = (lane < take) ? g_srcs[p + lane] : 0;   // one coalesced LDG / window
        int j = 0;
        for (; j + 8 <= take; j += 8) {
            uint2 v[8];
#pragma unroll
            for (int q = 0; q < 8; q++) {
                int s = __shfl_sync(0xffffffffu, myidx, j + q);
                v[q] = s2[(size_t)s * 32 + lane];
            }
#pragma unroll
            for (int q = 0; q < 8; q++) {
                float4 f = h4f(v[q]);
                acc.x += f.x; acc.y += f.y; acc.z += f.z; acc.w += f.w;
            }
        }
        for (; j < take; j++) {
            int s = __shfl_sync(0xffffffffu, myidx, j);
            float4 f = h4f(s2[(size_t)s * 32 + lane]);
            acc.x += f.x; acc.y += f.y; acc.z += f.z; acc.w += f.w;
        }
        p += take; nb -= take;
    }
    acc.x *= dw; acc.y *= dw; acc.z *= dw; acc.w *= dw;

    uint32_t h0 = pack_bf2(acc.x, acc.y);
    uint32_t h1 = pack_bf2(acc.z, acc.w);
    __nv_bfloat162 hv0 = *reinterpret_cast<__nv_bfloat162*>(&h0);
    __nv_bfloat162 hv1 = *reinterpret_cast<__nv_bfloat162*>(&h1);
    uint32_t l0 = pack_bf2(acc.x - __bfloat162float(hv0.x), acc.y - __bfloat162float(hv0.y));
    uint32_t l1 = pack_bf2(acc.z - __bfloat162float(hv1.x), acc.w - __bfloat162float(hv1.y));

    uint2* dh = (uint2*)((PHASE == 0) ? g_axhi : g_ahhi);
    uint2* dl = (uint2*)((PHASE == 0) ? g_axlo : g_ahlo);
    dh[(size_t)w * 32 + lane] = make_uint2(h0, h1);
    dl[(size_t)w * 32 + lane] = make_uint2(l0, l1);
}

// ================= HMMA GEMM: 128x128 tile, K=128, 3-term bf16 split ==============
// MODE 0: A = agg(x) hi/lo, B = W1; epilogue g_h(fp16) = dinv*relu(D+b1)
// MODE 1: A = agg(h) hi/lo, B = W2; split -> mu / logstd (+g_b2)
template <int MODE>
__global__ void __launch_bounds__(256) mma_gemm_kernel(const float* __restrict__ bias1,
                                                       float* __restrict__ out0,
                                                       float* __restrict__ out1, int n) {
    extern __shared__ __align__(16) char smem[];
    __nv_bfloat16* sAh = (__nv_bfloat16*)smem;      // 128 x KP
    __nv_bfloat16* sAl = sAh + 128 * KP;
    __nv_bfloat16* sBh = sAl + 128 * KP;
    __nv_bfloat16* sBl = sBh + 128 * KP;
    int tid = threadIdx.x;
    int lane = tid & 31, wid = tid >> 5;
    int row0 = blockIdx.x * 128;

    {
        const uint4* gAh = (const uint4*)((MODE == 0) ? g_axhi : g_ahhi);
        const uint4* gAl = (const uint4*)((MODE == 0) ? g_axlo : g_ahlo);
        const uint4* gBh = (const uint4*)((MODE == 0) ? g_w1hi : g_w2hi);
        const uint4* gBl = (const uint4*)((MODE == 0) ? g_w1lo : g_w2lo);
        for (int i = tid; i < 128 * 16; i += 256) {
            int r = i >> 4, c = i & 15;
            uint4 vh = make_uint4(0, 0, 0, 0), vl = vh;
            if (row0 + r < n) {
                vh = gAh[(size_t)(row0 + r) * 16 + c];
                vl = gAl[(size_t)(row0 + r) * 16 + c];
            }
            *(uint4*)&sAh[r * KP + c * 8] = vh;
            *(uint4*)&sAl[r * KP + c * 8] = vl;
            *(uint4*)&sBh[r * KP + c * 8] = gBh[i];
            *(uint4*)&sBl[r * KP + c * 8] = gBl[i];
        }
    }
    __syncthreads();

    int wm = wid & 3;
    int wn = wid >> 2;
    float d[2][8][4];
#pragma unroll
    for (int mt = 0; mt < 2; mt++)
#pragma unroll
        for (int nt = 0; nt < 8; nt++)
#pragma unroll
            for (int j = 0; j < 4; j++) d[mt][nt][j] = 0.f;

    uint32_t sbase = smem_u32(smem);
    int aRow  = wm * 32 + (lane & 15);
    int aKoff = (lane >> 4) << 3;
    int bRow  = wn * 64 + ((lane >> 4) << 3) + (lane & 7);
    int bKoff = ((lane >> 3) & 1) << 3;

#pragma unroll
    for (int term = 0; term < 3; term++) {
        uint32_t Abase = sbase + ((term == 2) ? 1 : 0) * 128 * KP * 2;
        uint32_t Bbase = sbase + 2 * 128 * KP * 2 + ((term == 1) ? 1 : 0) * 128 * KP * 2;
#pragma unroll
        for (int ks = 0; ks < 8; ks++) {
            uint32_t a[2][4];
#pragma unroll
            for (int mt = 0; mt < 2; mt++)
                ldsm_x4(a[mt], Abase + (uint32_t)(((aRow + mt * 16) * KP) + ks * 16 + aKoff) * 2);
            uint32_t b[8][2];
#pragma unroll
            for (int nt2 = 0; nt2 < 4; nt2++) {
                uint32_t r4[4];
                ldsm_x4(r4, Bbase + (uint32_t)(((bRow + nt2 * 16) * KP) + ks * 16 + bKoff) * 2);
                b[nt2 * 2 + 0][0] = r4[0]; b[nt2 * 2 + 0][1] = r4[1];
                b[nt2 * 2 + 1][0] = r4[2]; b[nt2 * 2 + 1][1] = r4[3];
            }
#pragma unroll
            for (int mt = 0; mt < 2; mt++)
#pragma unroll
                for (int nt = 0; nt < 8; nt++)
                    mma16816(d[mt][nt], a[mt], b[nt]);
        }
    }

    const float* bias = (MODE == 0) ? bias1 : g_b2;
    int quad = lane >> 2, tq = lane & 3;
#pragma unroll
    for (int mt = 0; mt < 2; mt++) {
        int ra = row0 + wm * 32 + mt * 16 + quad;
        int rb = ra + 8;
        float da = 0.f, db = 0.f;
        if (MODE == 0) {
            if (ra < n) da = g_dinv[ra];
            if (rb < n) db = g_dinv[rb];
        }
#pragma unroll
        for (int nt = 0; nt < 8; nt++) {
            int c = wn * 64 + nt * 8 + tq * 2;
            float b0 = bias[c], b1 = bias[c + 1];
            if (MODE == 0) {
                if (ra < n) {
                    __half2 hv = __floats2half2_rn(fmaxf(d[mt][nt][0] + b0, 0.f) * da,
                                                   fmaxf(d[mt][nt][1] + b1, 0.f) * da);
                    *(uint32_t*)&g_h[(size_t)ra * 128 + c] = *reinterpret_cast<uint32_t*>(&hv);
                }
                if (rb < n) {
                    __half2 hv = __floats2half2_rn(fmaxf(d[mt][nt][2] + b0, 0.f) * db,
                                                   fmaxf(d[mt][nt][3] + b1, 0.f) * db);
                    *(uint32_t*)&g_h[(size_t)rb * 128 + c] = *reinterpret_cast<uint32_t*>(&hv);
                }
            } else {
                float* dst = (c < 64) ? out0 : out1;
                int cc = (c < 64) ? c : c - 64;
                if (ra < n) {
                    float2 v = make_float2(d[mt][nt][0] + b0, d[mt][nt][1] + b1);
                    *(float2*)&dst[(size_t)ra * 64 + cc] = v;
                }
                if (rb < n) {
                    float2 v = make_float2(d[mt][nt][2] + b0, d[mt][nt][3] + b1);
                    *(float2*)&dst[(size_t)rb * 64 + cc] = v;
                }
            }
        }
    }
}

// ================= launch =================
#define SM_TOTAL (4 * 128 * KP * 2)

extern "C" void kernel_launch(void* const* d_in, const int* in_sizes, int n_in,
                              void* d_out, int out_size) {
    const float* x   = (const float*)d_in[0];
    const int*   ei  = (const int*)d_in[1];
    const float* W1  = (const float*)d_in[3];
    const float* b1  = (const float*)d_in[4];
    const float* Wmu = (const float*)d_in[5];
    const float* bmu = (const float*)d_in[6];
    const float* Wls = (const float*)d_in[7];
    const float* bls = (const float*)d_in[8];
    float* out = (float*)d_out;

    int n = in_sizes[0] / C;
    int e = in_sizes[1] / 2;
    const int* erow = ei;
    const int* ecol = ei + e;

    float* mu = out;
    float* ls = out + (size_t)n * 64;

    int nb_n = (n + 255) / 256;
    int nb_e = (e + 255) / 256;

    cudaFuncSetAttribute(mma_gemm_kernel<0>, cudaFuncAttributeMaxDynamicSharedMemorySize, SM_TOTAL);
    cudaFuncSetAttribute(mma_gemm_kernel<1>, cudaFuncAttributeMaxDynamicSharedMemorySize, SM_TOTAL);

    init_kernel<<<nb_n, 256>>>(n);
    count_kernel<<<nb_e, 256>>>(ecol, e);
    scanA_kernel<<<nb_n, 256>>>(n);
    scanB_kernel<<<1, NBMAX>>>(nb_n, n);
    scanC_kernel<<<nb_n, 256>>>(n);
    scatter_kernel<<<nb_e, 256>>>(erow, ecol, e);
    dim3 pw(128, 2);
    packW_kernel<<<pw, 128>>>(W1, Wmu, bmu, Wls, bls);
    scale_half_kernel<<<(n * 32 + 255) / 256, 256>>>(x, n);

    int agg_blocks = (n + 7) / 8;
    int gemm_blocks = (n + 127) / 128;

    agg_kernel<0><<<agg_blocks, 256>>>(n);
    mma_gemm_kernel<0><<<gemm_blocks, 256, SM_TOTAL>>>(b1, nullptr, nullptr, n);
    agg_kernel<1><<<agg_blocks, 256>>>(n);
    mma_gemm_kernel<1><<<gemm_blocks, 256, SM_TOTAL>>>(nullptr, mu, ls, n);
}

// round 12
// speedup vs baseline: 1.1439x; 1.1439x over previous
#include <cuda_runtime.h>
#include <cuda_bf16.h>
#include <cuda_fp16.h>
#include <cstdint>

#define MAXN 100000
#define MAXE 1600000
#define C 128
#define NBMAX 1024
#define KP 136   // padded K row length (bf16): 272B rows -> conflict-free ldmatrix
#define GEMM_GRID 148

// ================= static scratch =================
__device__ int   g_cnt[MAXN];
__device__ int   g_rowptr[MAXN + 1];
__device__ float g_dinv[MAXN];
__device__ int   g_srcs[MAXE];
__device__ int   g_rank[MAXE];
__device__ int   g_blocksum[NBMAX];
__device__ int   g_blockoff[NBMAX];
__device__ __half g_xh[(size_t)MAXN * C];           // dinv-scaled x in fp16
__device__ __half g_h [(size_t)MAXN * C];           // dinv*relu(layer1) in fp16
__device__ __nv_bfloat16 g_axhi[(size_t)MAXN * C];  // agg(x) bf16 hi
__device__ __nv_bfloat16 g_axlo[(size_t)MAXN * C];  // agg(x) bf16 lo
__device__ __nv_bfloat16 g_ahhi[(size_t)MAXN * C];  // agg(h) bf16 hi
__device__ __nv_bfloat16 g_ahlo[(size_t)MAXN * C];  // agg(h) bf16 lo
__device__ __nv_bfloat16 g_w1hi[C * C], g_w1lo[C * C];  // W1^T  [n][k] bf16 hi/lo
__device__ __nv_bfloat16 g_w2hi[C * C], g_w2lo[C * C];  // [Wmu|Wls]^T
__device__ float g_b2[C];

// ================= helpers =================
__device__ __forceinline__ uint32_t smem_u32(const void* p) {
    uint32_t a;
    asm("{ .reg .u64 t; cvta.to.shared.u64 t, %1; cvt.u32.u64 %0, t; }" : "=r"(a) : "l"(p));
    return a;
}
__device__ __forceinline__ void ldsm_x4(uint32_t* r, uint32_t addr) {
    asm volatile("ldmatrix.sync.aligned.m8n8.x4.shared.b16 {%0,%1,%2,%3}, [%4];"
        : "=r"(r[0]), "=r"(r[1]), "=r"(r[2]), "=r"(r[3]) : "r"(addr));
}
__device__ __forceinline__ void mma16816(float* d, const uint32_t* a, const uint32_t* b) {
    asm volatile("mma.sync.aligned.m16n8k16.row.col.f32.bf16.bf16.f32 "
        "{%0,%1,%2,%3}, {%4,%5,%6,%7}, {%8,%9}, {%0,%1,%2,%3};"
        : "+f"(d[0]), "+f"(d[1]), "+f"(d[2]), "+f"(d[3])
        : "r"(a[0]), "r"(a[1]), "r"(a[2]), "r"(a[3]), "r"(b[0]), "r"(b[1]));
}
__device__ __forceinline__ uint32_t pack_bf2(float a, float b) {
    __nv_bfloat162 t = __halves2bfloat162(__float2bfloat16_rn(a), __float2bfloat16_rn(b));
    return *reinterpret_cast<uint32_t*>(&t);
}
__device__ __forceinline__ float4 h4f(uint2 u) {
    float2 fa = __half22float2(*reinterpret_cast<__half2*>(&u.x));
    float2 fb = __half22float2(*reinterpret_cast<__half2*>(&u.y));
    return make_float4(fa.x, fa.y, fb.x, fb.y);
}

// ================= CSR build =================
__global__ void init_kernel(int n) {
    int i = blockIdx.x * blockDim.x + threadIdx.x;
    if (i < n) g_cnt[i] = 0;
}
// count + record per-edge rank (makes scatter atomic-free)
__global__ void count_kernel(const int* __restrict__ col, int e) {
    int i = blockIdx.x * blockDim.x + threadIdx.x;
    if (i < e) g_rank[i] = atomicAdd(&g_cnt[col[i]], 1);
}
__global__ void scanA_kernel(int n) {
    __shared__ int red[256];
    int i = blockIdx.x * 256 + threadIdx.x;
    red[threadIdx.x] = (i < n) ? g_cnt[i] : 0;
    __syncthreads();
    for (int off = 128; off > 0; off >>= 1) {
        if (threadIdx.x < off) red[threadIdx.x] += red[threadIdx.x + off];
        __syncthreads();
    }
    if (threadIdx.x == 0) g_blocksum[blockIdx.x] = red[0];
}
__global__ void scanB_kernel(int nb, int n) {
    __shared__ int s[NBMAX];
    int t = threadIdx.x;
    int v = (t < nb) ? g_blocksum[t] : 0;
    s[t] = v;
    __syncthreads();
    for (int off = 1; off < NBMAX; off <<= 1) {
        int u = (t >= off) ? s[t - off] : 0;
        __syncthreads();
        s[t] += u;
        __syncthreads();
    }
    if (t < nb) g_blockoff[t] = s[t] - v;
    if (t == NBMAX - 1) g_rowptr[n] = s[NBMAX - 1];
}
__global__ void scanC_kernel(int n) {
    __shared__ int s[256];
    int i = blockIdx.x * 256 + threadIdx.x;
    int c = (i < n) ? g_cnt[i] : 0;
    s[threadIdx.x] = c;
    __syncthreads();
    for (int off = 1; off < 256; off <<= 1) {
        int u = (threadIdx.x >= off) ? s[threadIdx.x - off] : 0;
        __syncthreads();
        s[threadIdx.x] += u;
        __syncthreads();
    }
    if (i < n) {
        g_rowptr[i] = g_blockoff[blockIdx.x] + s[threadIdx.x] - c;
        g_dinv[i]   = rsqrtf((float)(c + 1));
    }
}
// atomic-free scatter using precomputed ranks
__global__ void scatter_kernel(const int* __restrict__ row, const int* __restrict__ col, int e) {
    int i = blockIdx.x * blockDim.x + threadIdx.x;
    if (i < e) {
        int c = col[i];
        g_srcs[g_rowptr[c] + g_rank[i]] = row[i];
    }
}

// x -> dinv-scaled fp16 (streaming)
__global__ void scale_half_kernel(const float* __restrict__ x, int n) {
    int i = blockIdx.x * blockDim.x + threadIdx.x;
    if (i >= n * 32) return;
    float d = g_dinv[i >> 5];
    float4 v = ((const float4*)x)[i];
    __half2 a = __floats2half2_rn(v.x * d, v.y * d);
    __half2 b = __floats2half2_rn(v.z * d, v.w * d);
    ((uint2*)g_xh)[i] = make_uint2(*reinterpret_cast<uint32_t*>(&a),
                                   *reinterpret_cast<uint32_t*>(&b));
}

// pack transposed bf16 hi/lo W images: Bt[nn][k] = W[k][nn]
__global__ void packW_kernel(const float* __restrict__ W1,
                             const float* __restrict__ Wmu, const float* __restrict__ bmu,
                             const float* __restrict__ Wls, const float* __restrict__ bls) {
    int k = blockIdx.x;
    int nn = threadIdx.x;
    int layer = blockIdx.y;
    float w;
    if (layer == 0) w = W1[k * 128 + nn];
    else            w = (nn < 64) ? Wmu[k * 64 + nn] : Wls[k * 64 + (nn - 64)];
    __nv_bfloat16 bh = __float2bfloat16_rn(w);
    __nv_bfloat16 bl = __float2bfloat16_rn(w - __bfloat162float(bh));
    if (layer == 0) { g_w1hi[nn * 128 + k] = bh; g_w1lo[nn * 128 + k] = bl; }
    else {
        g_w2hi[nn * 128 + k] = bh; g_w2lo[nn * 128 + k] = bl;
        if (k == 0) g_b2[nn] = (nn < 64) ? bmu[nn] : bls[nn - 64];
    }
}

// ================= aggregation: warp/node, MLP=8 fp16 gather (R10 form) ============
// PHASE 0: src = g_xh -> g_axhi/lo       PHASE 1: src = g_h -> g_ahhi/lo
template <int PHASE>
__global__ void agg_kernel(int n) {
    int w = (blockIdx.x * blockDim.x + threadIdx.x) >> 5;
    int lane = threadIdx.x & 31;
    if (w >= n) return;
    const uint2* __restrict__ s2 = (PHASE == 0) ? (const uint2*)g_xh : (const uint2*)g_h;

    float dw = g_dinv[w];
    float4 acc = h4f(s2[(size_t)w * 32 + lane]);   // self term (pre-scaled by dinv)

    int p = g_rowptr[w];
    int end = g_rowptr[w + 1];
    for (; p + 8 <= end; p += 8) {
        int s[8];
#pragma unroll
        for (int j = 0; j < 8; j++) s[j] = g_srcs[p + j];
        uint2 v[8];
#pragma unroll
        for (int j = 0; j < 8; j++) v[j] = s2[(size_t)s[j] * 32 + lane];
#pragma unroll
        for (int j = 0; j < 8; j++) {
            float4 f = h4f(v[j]);
            acc.x += f.x; acc.y += f.y; acc.z += f.z; acc.w += f.w;
        }
    }
    for (; p + 4 <= end; p += 4) {
        int s[4];
#pragma unroll
        for (int j = 0; j < 4; j++) s[j] = g_srcs[p + j];
        uint2 v[4];
#pragma unroll
        for (int j = 0; j < 4; j++) v[j] = s2[(size_t)s[j] * 32 + lane];
#pragma unroll
        for (int j = 0; j < 4; j++) {
            float4 f = h4f(v[j]);
            acc.x += f.x; acc.y += f.y; acc.z += f.z; acc.w += f.w;
        }
    }
    for (; p < end; p++) {
        float4 f = h4f(s2[(size_t)g_srcs[p] * 32 + lane]);
        acc.x += f.x; acc.y += f.y; acc.z += f.z; acc.w += f.w;
    }
    acc.x *= dw; acc.y *= dw; acc.z *= dw; acc.w *= dw;

    uint32_t h0 = pack_bf2(acc.x, acc.y);
    uint32_t h1 = pack_bf2(acc.z, acc.w);
    __nv_bfloat162 hv0 = *reinterpret_cast<__nv_bfloat162*>(&h0);
    __nv_bfloat162 hv1 = *reinterpret_cast<__nv_bfloat162*>(&h1);
    uint32_t l0 = pack_bf2(acc.x - __bfloat162float(hv0.x), acc.y - __bfloat162float(hv0.y));
    uint32_t l1 = pack_bf2(acc.z - __bfloat162float(hv1.x), acc.w - __bfloat162float(hv1.y));

    uint2* dh = (uint2*)((PHASE == 0) ? g_axhi : g_ahhi);
    uint2* dl = (uint2*)((PHASE == 0) ? g_axlo : g_ahlo);
    dh[(size_t)w * 32 + lane] = make_uint2(h0, h1);
    dl[(size_t)w * 32 + lane] = make_uint2(l0, l1);
}

// ================= persistent HMMA GEMM: B staged once, loop row tiles =============
// MODE 0: A = agg(x) hi/lo, B = W1; epilogue g_h(fp16) = dinv*relu(D+b1)
// MODE 1: A = agg(h) hi/lo, B = W2; split -> mu / logstd (+g_b2)
template <int MODE>
__global__ void __launch_bounds__(256) mma_gemm_kernel(const float* __restrict__ bias1,
                                                       float* __restrict__ out0,
                                                       float* __restrict__ out1, int n) {
    extern __shared__ __align__(16) char smem[];
    __nv_bfloat16* sAh = (__nv_bfloat16*)smem;      // 128 x KP
    __nv_bfloat16* sAl = sAh + 128 * KP;
    __nv_bfloat16* sBh = sAl + 128 * KP;
    __nv_bfloat16* sBl = sBh + 128 * KP;
    int tid = threadIdx.x;
    int lane = tid & 31, wid = tid >> 5;

    // stage B once (persistent)
    {
        const uint4* gBh = (const uint4*)((MODE == 0) ? g_w1hi : g_w2hi);
        const uint4* gBl = (const uint4*)((MODE == 0) ? g_w1lo : g_w2lo);
        for (int i = tid; i < 128 * 16; i += 256) {
            int r = i >> 4, c = i & 15;
            *(uint4*)&sBh[r * KP + c * 8] = gBh[i];
            *(uint4*)&sBl[r * KP + c * 8] = gBl[i];
        }
    }

    const uint4* gAh = (const uint4*)((MODE == 0) ? g_axhi : g_ahhi);
    const uint4* gAl = (const uint4*)((MODE == 0) ? g_axlo : g_ahlo);
    const float* bias = (MODE == 0) ? bias1 : g_b2;

    int wm = wid & 3;
    int wn = wid >> 2;
    uint32_t sbase = smem_u32(smem);
    int aRow  = wm * 32 + (lane & 15);
    int aKoff = (lane >> 4) << 3;
    int bRow  = wn * 64 + ((lane >> 4) << 3) + (lane & 7);
    int bKoff = ((lane >> 3) & 1) << 3;
    int quad = lane >> 2, tq = lane & 3;

    int ntiles = (n + 127) >> 7;
    for (int tile = blockIdx.x; tile < ntiles; tile += gridDim.x) {
        int row0 = tile << 7;
        __syncthreads();   // previous iteration's ldsm of sA complete
        for (int i = tid; i < 128 * 16; i += 256) {
            int r = i >> 4, c = i & 15;
            uint4 vh = make_uint4(0, 0, 0, 0), vl = vh;
            if (row0 + r < n) {
                vh = gAh[(size_t)(row0 + r) * 16 + c];
                vl = gAl[(size_t)(row0 + r) * 16 + c];
            }
            *(uint4*)&sAh[r * KP + c * 8] = vh;
            *(uint4*)&sAl[r * KP + c * 8] = vl;
        }
        __syncthreads();

        float d[2][8][4];
#pragma unroll
        for (int mt = 0; mt < 2; mt++)
#pragma unroll
            for (int nt = 0; nt < 8; nt++)
#pragma unroll
                for (int j = 0; j < 4; j++) d[mt][nt][j] = 0.f;

#pragma unroll
        for (int term = 0; term < 3; term++) {
            uint32_t Abase = sbase + ((term == 2) ? 1 : 0) * 128 * KP * 2;
            uint32_t Bbase = sbase + 2 * 128 * KP * 2 + ((term == 1) ? 1 : 0) * 128 * KP * 2;
#pragma unroll
            for (int ks = 0; ks < 8; ks++) {
                uint32_t a[2][4];
#pragma unroll
                for (int mt = 0; mt < 2; mt++)
                    ldsm_x4(a[mt], Abase + (uint32_t)(((aRow + mt * 16) * KP) + ks * 16 + aKoff) * 2);
                uint32_t b[8][2];
#pragma unroll
                for (int nt2 = 0; nt2 < 4; nt2++) {
                    uint32_t r4[4];
                    ldsm_x4(r4, Bbase + (uint32_t)(((bRow + nt2 * 16) * KP) + ks * 16 + bKoff) * 2);
                    b[nt2 * 2 + 0][0] = r4[0]; b[nt2 * 2 + 0][1] = r4[1];
                    b[nt2 * 2 + 1][0] = r4[2]; b[nt2 * 2 + 1][1] = r4[3];
                }
#pragma unroll
                for (int mt = 0; mt < 2; mt++)
#pragma unroll
                    for (int nt = 0; nt < 8; nt++)
                        mma16816(d[mt][nt], a[mt], b[nt]);
            }
        }

        // epilogue (registers only)
#pragma unroll
        for (int mt = 0; mt < 2; mt++) {
            int ra = row0 + wm * 32 + mt * 16 + quad;
            int rb = ra + 8;
            float da = 0.f, db = 0.f;
            if (MODE == 0) {
                if (ra < n) da = g_dinv[ra];
                if (rb < n) db = g_dinv[rb];
            }
#pragma unroll
            for (int nt = 0; nt < 8; nt++) {
                int c = wn * 64 + nt * 8 + tq * 2;
                float b0 = bias[c], b1 = bias[c + 1];
                if (MODE == 0) {
                    if (ra < n) {
                        __half2 hv = __floats2half2_rn(fmaxf(d[mt][nt][0] + b0, 0.f) * da,
                                                       fmaxf(d[mt][nt][1] + b1, 0.f) * da);
                        *(uint32_t*)&g_h[(size_t)ra * 128 + c] = *reinterpret_cast<uint32_t*>(&hv);
                    }
                    if (rb < n) {
                        __half2 hv = __floats2half2_rn(fmaxf(d[mt][nt][2] + b0, 0.f) * db,
                                                       fmaxf(d[mt][nt][3] + b1, 0.f) * db);
                        *(uint32_t*)&g_h[(size_t)rb * 128 + c] = *reinterpret_cast<uint32_t*>(&hv);
                    }
                } else {
                    float* dst = (c < 64) ? out0 : out1;
                    int cc = (c < 64) ? c : c - 64;
                    if (ra < n) {
                        float2 v = make_float2(d[mt][nt][0] + b0, d[mt][nt][1] + b1);
                        *(float2*)&dst[(size_t)ra * 64 + cc] = v;
                    }
                    if (rb < n) {
                        float2 v = make_float2(d[mt][nt][2] + b0, d[mt][nt][3] + b1);
                        *(float2*)&dst[(size_t)rb * 64 + cc] = v;
                    }
                }
            }
        }
    }
}

// ================= launch =================
#define SM_TOTAL (4 * 128 * KP * 2)

extern "C" void kernel_launch(void* const* d_in, const int* in_sizes, int n_in,
                              void* d_out, int out_size) {
    const float* x   = (const float*)d_in[0];
    const int*   ei  = (const int*)d_in[1];
    const float* W1  = (const float*)d_in[3];
    const float* b1  = (const float*)d_in[4];
    const float* Wmu = (const float*)d_in[5];
    const float* bmu = (const float*)d_in[6];
    const float* Wls = (const float*)d_in[7];
    const float* bls = (const float*)d_in[8];
    float* out = (float*)d_out;

    int n = in_sizes[0] / C;
    int e = in_sizes[1] / 2;
    const int* erow = ei;
    const int* ecol = ei + e;

    float* mu = out;
    float* ls = out + (size_t)n * 64;

    int nb_n = (n + 255) / 256;
    int nb_e = (e + 255) / 256;

    cudaFuncSetAttribute(mma_gemm_kernel<0>, cudaFuncAttributeMaxDynamicSharedMemorySize, SM_TOTAL);
    cudaFuncSetAttribute(mma_gemm_kernel<1>, cudaFuncAttributeMaxDynamicSharedMemorySize, SM_TOTAL);

    init_kernel<<<nb_n, 256>>>(n);
    count_kernel<<<nb_e, 256>>>(ecol, e);
    scanA_kernel<<<nb_n, 256>>>(n);
    scanB_kernel<<<1, NBMAX>>>(nb_n, n);
    scanC_kernel<<<nb_n, 256>>>(n);
    scatter_kernel<<<nb_e, 256>>>(erow, ecol, e);
    dim3 pw(128, 2);
    packW_kernel<<<pw, 128>>>(W1, Wmu, bmu, Wls, bls);
    scale_half_kernel<<<(n * 32 + 255) / 256, 256>>>(x, n);

    int agg_blocks = (n + 7) / 8;

    agg_kernel<0><<<agg_blocks, 256>>>(n);
    mma_gemm_kernel<0><<<GEMM_GRID, 256, SM_TOTAL>>>(b1, nullptr, nullptr, n);
    agg_kernel<1><<<agg_blocks, 256>>>(n);
    mma_gemm_kernel<1><<<GEMM_GRID, 256, SM_TOTAL>>>(nullptr, mu, ls, n);
}

// round 13
// speedup vs baseline: 1.1558x; 1.0104x over previous
#include <cuda_runtime.h>
#include <cuda_bf16.h>
#include <cuda_fp16.h>
#include <cstdint>

#define MAXN 100000
#define MAXE 1600000
#define C 128
#define NBMAX 1024
#define KP 136   // padded K row length (bf16): 272B rows -> conflict-free ldmatrix
#define GEMM_GRID 148

// ================= static scratch =================
__device__ int   g_cnt[MAXN];
__device__ int   g_rowptr[MAXN + 1];
__device__ float g_dinv[MAXN];
__device__ int   g_srcs[MAXE];
__device__ int   g_rank[MAXE];
__device__ int   g_blocksum[NBMAX];
__device__ int   g_blockoff[NBMAX];
__device__ __half g_xh[(size_t)MAXN * C];   // dinv-scaled x in fp16
__device__ __half g_h [(size_t)MAXN * C];   // dinv*relu(layer1) in fp16
__device__ __half g_ax[(size_t)MAXN * C];   // agg(x) fp16 (split to bf16 hi/lo in GEMM)
__device__ __half g_ah[(size_t)MAXN * C];   // agg(h) fp16
__device__ __nv_bfloat16 g_w1hi[C * C], g_w1lo[C * C];  // W1^T  [n][k] bf16 hi/lo
__device__ __nv_bfloat16 g_w2hi[C * C], g_w2lo[C * C];  // [Wmu|Wls]^T
__device__ float g_b2[C];

// ================= helpers =================
__device__ __forceinline__ uint32_t smem_u32(const void* p) {
    uint32_t a;
    asm("{ .reg .u64 t; cvta.to.shared.u64 t, %1; cvt.u32.u64 %0, t; }" : "=r"(a) : "l"(p));
    return a;
}
__device__ __forceinline__ void ldsm_x4(uint32_t* r, uint32_t addr) {
    asm volatile("ldmatrix.sync.aligned.m8n8.x4.shared.b16 {%0,%1,%2,%3}, [%4];"
        : "=r"(r[0]), "=r"(r[1]), "=r"(r[2]), "=r"(r[3]) : "r"(addr));
}
__device__ __forceinline__ void mma16816(float* d, const uint32_t* a, const uint32_t* b) {
    asm volatile("mma.sync.aligned.m16n8k16.row.col.f32.bf16.bf16.f32 "
        "{%0,%1,%2,%3}, {%4,%5,%6,%7}, {%8,%9}, {%0,%1,%2,%3};"
        : "+f"(d[0]), "+f"(d[1]), "+f"(d[2]), "+f"(d[3])
        : "r"(a[0]), "r"(a[1]), "r"(a[2]), "r"(a[3]), "r"(b[0]), "r"(b[1]));
}
__device__ __forceinline__ uint32_t pack_bf2(float a, float b) {
    __nv_bfloat162 t = __halves2bfloat162(__float2bfloat16_rn(a), __float2bfloat16_rn(b));
    return *reinterpret_cast<uint32_t*>(&t);
}
__device__ __forceinline__ float4 h4f(uint2 u) {
    float2 fa = __half22float2(*reinterpret_cast<__half2*>(&u.x));
    float2 fb = __half22float2(*reinterpret_cast<__half2*>(&u.y));
    return make_float4(fa.x, fa.y, fb.x, fb.y);
}

// ================= CSR build =================
// init g_cnt + pack W images (independent work, one launch)
__global__ void init_pack_kernel(int n, int nb_n,
                                 const float* __restrict__ W1,
                                 const float* __restrict__ Wmu, const float* __restrict__ bmu,
                                 const float* __restrict__ Wls, const float* __restrict__ bls) {
    if ((int)blockIdx.x < nb_n) {
        int i = blockIdx.x * blockDim.x + threadIdx.x;
        if (i < n) g_cnt[i] = 0;
    } else {
        int pb = blockIdx.x - nb_n;          // 0..255
        int k = pb & 127;
        int layer = pb >> 7;
        int nn = threadIdx.x;
        if (nn < 128) {
            float w;
            if (layer == 0) w = W1[k * 128 + nn];
            else            w = (nn < 64) ? Wmu[k * 64 + nn] : Wls[k * 64 + (nn - 64)];
            __nv_bfloat16 bh = __float2bfloat16_rn(w);
            __nv_bfloat16 bl = __float2bfloat16_rn(w - __bfloat162float(bh));
            if (layer == 0) { g_w1hi[nn * 128 + k] = bh; g_w1lo[nn * 128 + k] = bl; }
            else {
                g_w2hi[nn * 128 + k] = bh; g_w2lo[nn * 128 + k] = bl;
                if (k == 0) g_b2[nn] = (nn < 64) ? bmu[nn] : bls[nn - 64];
            }
        }
    }
}
// count + record per-edge rank (makes scatter atomic-free)
__global__ void count_kernel(const int* __restrict__ col, int e) {
    int i = blockIdx.x * blockDim.x + threadIdx.x;
    if (i < e) g_rank[i] = atomicAdd(&g_cnt[col[i]], 1);
}
__global__ void scanA_kernel(int n) {
    __shared__ int red[256];
    int i = blockIdx.x * 256 + threadIdx.x;
    red[threadIdx.x] = (i < n) ? g_cnt[i] : 0;
    __syncthreads();
    for (int off = 128; off > 0; off >>= 1) {
        if (threadIdx.x < off) red[threadIdx.x] += red[threadIdx.x + off];
        __syncthreads();
    }
    if (threadIdx.x == 0) g_blocksum[blockIdx.x] = red[0];
}
__global__ void scanB_kernel(int nb, int n) {
    __shared__ int s[NBMAX];
    int t = threadIdx.x;
    int v = (t < nb) ? g_blocksum[t] : 0;
    s[t] = v;
    __syncthreads();
    for (int off = 1; off < NBMAX; off <<= 1) {
        int u = (t >= off) ? s[t - off] : 0;
        __syncthreads();
        s[t] += u;
        __syncthreads();
    }
    if (t < nb) g_blockoff[t] = s[t] - v;
    if (t == NBMAX - 1) g_rowptr[n] = s[NBMAX - 1];
}
// scan + dinv + fused x->fp16 pre-scale
__global__ void scanC_kernel(const float* __restrict__ x, int n) {
    __shared__ int s[256];
    __shared__ float sd[256];
    int i = blockIdx.x * 256 + threadIdx.x;
    int c = (i < n) ? g_cnt[i] : 0;
    s[threadIdx.x] = c;
    __syncthreads();
    for (int off = 1; off < 256; off <<= 1) {
        int u = (threadIdx.x >= off) ? s[threadIdx.x - off] : 0;
        __syncthreads();
        s[threadIdx.x] += u;
        __syncthreads();
    }
    float d = rsqrtf((float)(c + 1));
    if (i < n) {
        g_rowptr[i] = g_blockoff[blockIdx.x] + s[threadIdx.x] - c;
        g_dinv[i]   = d;
    }
    sd[threadIdx.x] = d;
    __syncthreads();

    // scale this block's 256 node rows: x(fp32) -> g_xh(fp16, dinv-scaled)
    size_t base = (size_t)blockIdx.x * 256;
    int lim = n - (int)base; if (lim > 256) lim = 256;
    if (lim <= 0) return;
    for (int j = threadIdx.x; j < lim * 32; j += 256) {
        int local = j >> 5;
        float dv = sd[local];
        float4 v = ((const float4*)x)[(base + local) * 32 + (j & 31)];
        __half2 a = __floats2half2_rn(v.x * dv, v.y * dv);
        __half2 b = __floats2half2_rn(v.z * dv, v.w * dv);
        ((uint2*)g_xh)[(base + local) * 32 + (j & 31)] =
            make_uint2(*reinterpret_cast<uint32_t*>(&a), *reinterpret_cast<uint32_t*>(&b));
    }
}
// atomic-free scatter using precomputed ranks
__global__ void scatter_kernel(const int* __restrict__ row, const int* __restrict__ col, int e) {
    int i = blockIdx.x * blockDim.x + threadIdx.x;
    if (i < e) {
        int c = col[i];
        g_srcs[g_rowptr[c] + g_rank[i]] = row[i];
    }
}

// ================= aggregation: warp/node, MLP=8 fp16 gather -> fp16 out ===========
// PHASE 0: src = g_xh -> g_ax       PHASE 1: src = g_h -> g_ah
template <int PHASE>
__global__ void agg_kernel(int n) {
    int w = (blockIdx.x * blockDim.x + threadIdx.x) >> 5;
    int lane = threadIdx.x & 31;
    if (w >= n) return;
    const uint2* __restrict__ s2 = (PHASE == 0) ? (const uint2*)g_xh : (const uint2*)g_h;

    float dw = g_dinv[w];
    float4 acc = h4f(s2[(size_t)w * 32 + lane]);   // self term (pre-scaled by dinv)

    int p = g_rowptr[w];
    int end = g_rowptr[w + 1];
    for (; p + 8 <= end; p += 8) {
        int s[8];
#pragma unroll
        for (int j = 0; j < 8; j++) s[j] = g_srcs[p + j];
        uint2 v[8];
#pragma unroll
        for (int j = 0; j < 8; j++) v[j] = s2[(size_t)s[j] * 32 + lane];
#pragma unroll
        for (int j = 0; j < 8; j++) {
            float4 f = h4f(v[j]);
            acc.x += f.x; acc.y += f.y; acc.z += f.z; acc.w += f.w;
        }
    }
    for (; p + 4 <= end; p += 4) {
        int s[4];
#pragma unroll
        for (int j = 0; j < 4; j++) s[j] = g_srcs[p + j];
        uint2 v[4];
#pragma unroll
        for (int j = 0; j < 4; j++) v[j] = s2[(size_t)s[j] * 32 + lane];
#pragma unroll
        for (int j = 0; j < 4; j++) {
            float4 f = h4f(v[j]);
            acc.x += f.x; acc.y += f.y; acc.z += f.z; acc.w += f.w;
        }
    }
    for (; p < end; p++) {
        float4 f = h4f(s2[(size_t)g_srcs[p] * 32 + lane]);
        acc.x += f.x; acc.y += f.y; acc.z += f.z; acc.w += f.w;
    }
    acc.x *= dw; acc.y *= dw; acc.z *= dw; acc.w *= dw;

    __half2 a = __floats2half2_rn(acc.x, acc.y);
    __half2 b = __floats2half2_rn(acc.z, acc.w);
    uint2* dst = (uint2*)((PHASE == 0) ? g_ax : g_ah);
    dst[(size_t)w * 32 + lane] = make_uint2(*reinterpret_cast<uint32_t*>(&a),
                                            *reinterpret_cast<uint32_t*>(&b));
}

// ================= persistent HMMA GEMM: B staged once, loop row tiles =============
// A read as fp16, split exactly into bf16 hi/lo during staging.
// MODE 0: A = g_ax, B = W1; epilogue g_h(fp16) = dinv*relu(D+b1)
// MODE 1: A = g_ah, B = W2; split -> mu / logstd (+g_b2)
template <int MODE>
__global__ void __launch_bounds__(256) mma_gemm_kernel(const float* __restrict__ bias1,
                                                       float* __restrict__ out0,
                                                       float* __restrict__ out1, int n) {
    extern __shared__ __align__(16) char smem[];
    __nv_bfloat16* sAh = (__nv_bfloat16*)smem;      // 128 x KP
    __nv_bfloat16* sAl = sAh + 128 * KP;
    __nv_bfloat16* sBh = sAl + 128 * KP;
    __nv_bfloat16* sBl = sBh + 128 * KP;
    int tid = threadIdx.x;
    int lane = tid & 31, wid = tid >> 5;

    // stage B once (persistent)
    {
        const uint4* gBh = (const uint4*)((MODE == 0) ? g_w1hi : g_w2hi);
        const uint4* gBl = (const uint4*)((MODE == 0) ? g_w1lo : g_w2lo);
        for (int i = tid; i < 128 * 16; i += 256) {
            int r = i >> 4, c = i & 15;
            *(uint4*)&sBh[r * KP + c * 8] = gBh[i];
            *(uint4*)&sBl[r * KP + c * 8] = gBl[i];
        }
    }

    const uint4* gA = (const uint4*)((MODE == 0) ? g_ax : g_ah);
    const float* bias = (MODE == 0) ? bias1 : g_b2;

    int wm = wid & 3;
    int wn = wid >> 2;
    uint32_t sbase = smem_u32(smem);
    int aRow  = wm * 32 + (lane & 15);
    int aKoff = (lane >> 4) << 3;
    int bRow  = wn * 64 + ((lane >> 4) << 3) + (lane & 7);
    int bKoff = ((lane >> 3) & 1) << 3;
    int quad = lane >> 2, tq = lane & 3;

    int ntiles = (n + 127) >> 7;
    for (int tile = blockIdx.x; tile < ntiles; tile += gridDim.x) {
        int row0 = tile << 7;
        __syncthreads();   // previous iteration's ldsm of sA complete
        for (int i = tid; i < 128 * 16; i += 256) {
            int r = i >> 4, c = i & 15;
            uint4 v = make_uint4(0, 0, 0, 0);
            if (row0 + r < n) v = gA[(size_t)(row0 + r) * 8 + (c >> 1) * 2 + (c & 1)];
            // NOTE: A row = 128 fp16 = 16 uint4? No: 128 fp16 = 256B = 16 uint4. c in [0,16).
            v = (row0 + r < n) ? gA[(size_t)(row0 + r) * 16 + c] : make_uint4(0, 0, 0, 0);
            // split 8 fp16 -> bf16 hi/lo (exact: fp16 mantissa fits in hi+lo)
            const __half2* hp = (const __half2*)&v;
            uint32_t hiw[4], low[4];
#pragma unroll
            for (int q = 0; q < 4; q++) {
                float2 f = __half22float2(hp[q]);
                __nv_bfloat16 bx = __float2bfloat16_rn(f.x);
                __nv_bfloat16 by = __float2bfloat16_rn(f.y);
                __nv_bfloat162 hv = __halves2bfloat162(bx, by);
                hiw[q] = *reinterpret_cast<uint32_t*>(&hv);
                low[q] = pack_bf2(f.x - __bfloat162float(bx), f.y - __bfloat162float(by));
            }
            *(uint4*)&sAh[r * KP + c * 8] = make_uint4(hiw[0], hiw[1], hiw[2], hiw[3]);
            *(uint4*)&sAl[r * KP + c * 8] = make_uint4(low[0], low[1], low[2], low[3]);
        }
        __syncthreads();

        float d[2][8][4];
#pragma unroll
        for (int mt = 0; mt < 2; mt++)
#pragma unroll
            for (int nt = 0; nt < 8; nt++)
#pragma unroll
                for (int j = 0; j < 4; j++) d[mt][nt][j] = 0.f;

#pragma unroll
        for (int term = 0; term < 3; term++) {
            uint32_t Abase = sbase + ((term == 2) ? 1 : 0) * 128 * KP * 2;
            uint32_t Bbase = sbase + 2 * 128 * KP * 2 + ((term == 1) ? 1 : 0) * 128 * KP * 2;
#pragma unroll
            for (int ks = 0; ks < 8; ks++) {
                uint32_t a[2][4];
#pragma unroll
                for (int mt = 0; mt < 2; mt++)
                    ldsm_x4(a[mt], Abase + (uint32_t)(((aRow + mt * 16) * KP) + ks * 16 + aKoff) * 2);
                uint32_t b[8][2];
#pragma unroll
                for (int nt2 = 0; nt2 < 4; nt2++) {
                    uint32_t r4[4];
                    ldsm_x4(r4, Bbase + (uint32_t)(((bRow + nt2 * 16) * KP) + ks * 16 + bKoff) * 2);
                    b[nt2 * 2 + 0][0] = r4[0]; b[nt2 * 2 + 0][1] = r4[1];
                    b[nt2 * 2 + 1][0] = r4[2]; b[nt2 * 2 + 1][1] = r4[3];
                }
#pragma unroll
                for (int mt = 0; mt < 2; mt++)
#pragma unroll
                    for (int nt = 0; nt < 8; nt++)
                        mma16816(d[mt][nt], a[mt], b[nt]);
            }
        }

        // epilogue (registers only)
#pragma unroll
        for (int mt = 0; mt < 2; mt++) {
            int ra = row0 + wm * 32 + mt * 16 + quad;
            int rb = ra + 8;
            float da = 0.f, db = 0.f;
            if (MODE == 0) {
                if (ra < n) da = g_dinv[ra];
                if (rb < n) db = g_dinv[rb];
            }
#pragma unroll
            for (int nt = 0; nt < 8; nt++) {
                int c = wn * 64 + nt * 8 + tq * 2;
                float b0 = bias[c], b1 = bias[c + 1];
                if (MODE == 0) {
                    if (ra < n) {
                        __half2 hv = __floats2half2_rn(fmaxf(d[mt][nt][0] + b0, 0.f) * da,
                                                       fmaxf(d[mt][nt][1] + b1, 0.f) * da);
                        *(uint32_t*)&g_h[(size_t)ra * 128 + c] = *reinterpret_cast<uint32_t*>(&hv);
                    }
                    if (rb < n) {
                        __half2 hv = __floats2half2_rn(fmaxf(d[mt][nt][2] + b0, 0.f) * db,
                                                       fmaxf(d[mt][nt][3] + b1, 0.f) * db);
                        *(uint32_t*)&g_h[(size_t)rb * 128 + c] = *reinterpret_cast<uint32_t*>(&hv);
                    }
                } else {
                    float* dst = (c < 64) ? out0 : out1;
                    int cc = (c < 64) ? c : c - 64;
                    if (ra < n) {
                        float2 v = make_float2(d[mt][nt][0] + b0, d[mt][nt][1] + b1);
                        *(float2*)&dst[(size_t)ra * 64 + cc] = v;
                    }
                    if (rb < n) {
                        float2 v = make_float2(d[mt][nt][2] + b0, d[mt][nt][3] + b1);
                        *(float2*)&dst[(size_t)rb * 64 + cc] = v;
                    }
                }
            }
        }
    }
}

// ================= launch =================
#define SM_TOTAL (4 * 128 * KP * 2)

extern "C" void kernel_launch(void* const* d_in, const int* in_sizes, int n_in,
                              void* d_out, int out_size) {
    const float* x   = (const float*)d_in[0];
    const int*   ei  = (const int*)d_in[1];
    const float* W1  = (const float*)d_in[3];
    const float* b1  = (const float*)d_in[4];
    const float* Wmu = (const float*)d_in[5];
    const float* bmu = (const float*)d_in[6];
    const float* Wls = (const float*)d_in[7];
    const float* bls = (const float*)d_in[8];
    float* out = (float*)d_out;

    int n = in_sizes[0] / C;
    int e = in_sizes[1] / 2;
    const int* erow = ei;
    const int* ecol = ei + e;

    float* mu = out;
    float* ls = out + (size_t)n * 64;

    int nb_n = (n + 255) / 256;
    int nb_e = (e + 255) / 256;

    cudaFuncSetAttribute(mma_gemm_kernel<0>, cudaFuncAttributeMaxDynamicSharedMemorySize, SM_TOTAL);
    cudaFuncSetAttribute(mma_gemm_kernel<1>, cudaFuncAttributeMaxDynamicSharedMemorySize, SM_TOTAL);

    init_pack_kernel<<<nb_n + 256, 256>>>(n, nb_n, W1, Wmu, bmu, Wls, bls);
    count_kernel<<<nb_e, 256>>>(ecol, e);
    scanA_kernel<<<nb_n, 256>>>(n);
    scanB_kernel<<<1, NBMAX>>>(nb_n, n);
    scanC_kernel<<<nb_n, 256>>>(x, n);
    scatter_kernel<<<nb_e, 256>>>(erow, ecol, e);

    int agg_blocks = (n + 7) / 8;

    agg_kernel<0><<<agg_blocks, 256>>>(n);
    mma_gemm_kernel<0><<<GEMM_GRID, 256, SM_TOTAL>>>(b1, nullptr, nullptr, n);
    agg_kernel<1><<<agg_blocks, 256>>>(n);
    mma_gemm_kernel<1><<<GEMM_GRID, 256, SM_TOTAL>>>(nullptr, mu, ls, n);
}